// round 6
// baseline (speedup 1.0000x reference)
#include <cuda_runtime.h>
#include <cuda_bf16.h>
#include <cstdint>

#define N_NODES 59392
#define F_IN    116
#define H_DIM   256
#define N_EDGES 950272
#define E_DIM   5
#define EMB     16
#define K_IN    (F_IN + EMB)   // 132
#define BN_EPS  1e-5f

// ---------------- scratch (no allocations allowed) ----------------
__device__ float g_h  [(size_t)N_NODES * H_DIM];
__device__ float g_agg[(size_t)N_NODES * H_DIM];
__device__ float g_tmp[(size_t)N_NODES * H_DIM];
__device__ float g_sum[H_DIM];
__device__ float g_sumsq[H_DIM];
__device__ float g_scale[H_DIM];
__device__ float g_shift[H_DIM];
__device__ int   g_src[N_EDGES];
__device__ int   g_dst[N_EDGES];
__device__ int   g_gid[N_NODES];
__device__ int   g_is64;

// ---------------- dtype probe: int64 vs int32 index buffers ----------------
__global__ void detect_kernel(const int* __restrict__ ei_words) {
    if (threadIdx.x == 0) {
        int all_zero = 1;
        for (int i = 1; i < 256; i += 2)
            if (ei_words[i] != 0) { all_zero = 0; break; }
        g_is64 = all_zero;
    }
}

// normalize edge_index and group_ids into int32 scratch (works for both dtypes)
__global__ __launch_bounds__(256)
void convert_kernel(const void* __restrict__ ei, const void* __restrict__ gid) {
    const int is64 = g_is64;
    const long long* ei64  = (const long long*)ei;
    const int*       ei32  = (const int*)ei;
    const long long* gid64 = (const long long*)gid;
    const int*       gid32 = (const int*)gid;
    size_t stride = (size_t)gridDim.x * blockDim.x;
    for (size_t e = (size_t)blockIdx.x * blockDim.x + threadIdx.x; e < N_EDGES; e += stride) {
        if (is64) {
            g_src[e] = (int)ei64[e];
            g_dst[e] = (int)ei64[(size_t)N_EDGES + e];
        } else {
            g_src[e] = ei32[e];
            g_dst[e] = ei32[(size_t)N_EDGES + e];
        }
    }
    for (size_t n = (size_t)blockIdx.x * blockDim.x + threadIdx.x; n < N_NODES; n += stride)
        g_gid[n] = is64 ? (int)gid64[n] : gid32[n];
}

// ---------------- zero agg + stats ----------------
__global__ __launch_bounds__(256)
void zero_kernel() {
    size_t total4 = (size_t)N_NODES * H_DIM / 4;
    size_t stride = (size_t)gridDim.x * blockDim.x;
    float4* a4 = reinterpret_cast<float4*>(g_agg);
    float4 z = make_float4(0.f, 0.f, 0.f, 0.f);
    for (size_t i = (size_t)blockIdx.x * blockDim.x + threadIdx.x; i < total4; i += stride)
        a4[i] = z;
    if (blockIdx.x == 0 && threadIdx.x < H_DIM) {
        g_sum[threadIdx.x]   = 0.0f;
        g_sumsq[threadIdx.x] = 0.0f;
    }
}

// ---------------- mma / ldmatrix helpers ----------------
__device__ __forceinline__ void ldsm_x4(unsigned& r0, unsigned& r1, unsigned& r2, unsigned& r3,
                                        unsigned addr) {
    asm volatile("ldmatrix.sync.aligned.m8n8.x4.shared.b16 {%0,%1,%2,%3}, [%4];"
                 : "=r"(r0), "=r"(r1), "=r"(r2), "=r"(r3) : "r"(addr));
}
__device__ __forceinline__ void mma_bf16(float* c, const unsigned* a, unsigned b0, unsigned b1) {
    asm volatile(
        "mma.sync.aligned.m16n8k16.row.col.f32.bf16.bf16.f32 "
        "{%0,%1,%2,%3}, {%4,%5,%6,%7}, {%8,%9}, {%0,%1,%2,%3};\n"
        : "+f"(c[0]), "+f"(c[1]), "+f"(c[2]), "+f"(c[3])
        : "r"(a[0]), "r"(a[1]), "r"(a[2]), "r"(a[3]), "r"(b0), "r"(b1));
}
__device__ __forceinline__ void split_bf16(float v, __nv_bfloat16& hi, __nv_bfloat16& lo) {
    hi = __float2bfloat16_rn(v);
    lo = __float2bfloat16_rn(v - __bfloat162float(hi));
}

// ---------------- 3xBF16 tensor-core GEMM ----------------
// dst[M x 256] = relu(A[M x K] @ W[K x 256] + bias)
// MODE 0: A = concat(x, group_emb[g_gid])         (K = 132), dst = g_h
// MODE 1: A = (g_h*scale+shift) + g_agg           (K = 256), dst = g_tmp
// MODE 2: A = g_tmp                               (K = 256), dst = out param
// BM=128, BN=128, BK=32, 256 threads = 8 warps (4x2), warp tile 32x64.
#define ASTR 40   // smem row stride in bf16 halves (80B = 5x16B units, ldmatrix conflict-free)

template <int MODE>
__global__ __launch_bounds__(256, 2)
void gemm_kernel(const float* __restrict__ X,
                 const float* __restrict__ Gemb,
                 const float* __restrict__ W,
                 const float* __restrict__ bias,
                 float* __restrict__ out_param,
                 int K)
{
    const int BM = 128, BK = 32;
    __shared__ __align__(16) __nv_bfloat16 As_hi[BM * ASTR];   // [m][k]
    __shared__ __align__(16) __nv_bfloat16 As_lo[BM * ASTR];
    __shared__ __align__(16) __nv_bfloat16 Bs_hi[128 * ASTR];  // [n][k] (transposed)
    __shared__ __align__(16) __nv_bfloat16 Bs_lo[128 * ASTR];
    __shared__ int sgid[BM];

    const int row0 = blockIdx.x * BM;
    const int col0 = blockIdx.y * 128;
    const int tid  = threadIdx.x;
    const int wid  = tid >> 5;
    const int lane = tid & 31;
    const int wm   = (wid & 3) * 32;   // warp row offset
    const int wn   = (wid >> 2) * 64;  // warp col offset
    const int lrow = lane >> 2;        // 0..7

    const unsigned as_hi_b = (unsigned)__cvta_generic_to_shared(As_hi);
    const unsigned as_lo_b = (unsigned)__cvta_generic_to_shared(As_lo);
    const unsigned bs_hi_b = (unsigned)__cvta_generic_to_shared(Bs_hi);
    const unsigned bs_lo_b = (unsigned)__cvta_generic_to_shared(Bs_lo);

    if (MODE == 0) {
        if (tid < BM) sgid[tid] = g_gid[row0 + tid];
        __syncthreads();
    }

    float acc[2][8][4];
#pragma unroll
    for (int mt = 0; mt < 2; mt++)
#pragma unroll
        for (int nt = 0; nt < 8; nt++)
#pragma unroll
            for (int i = 0; i < 4; i++) acc[mt][nt][i] = 0.0f;

    // ldmatrix lane-address components (in halves)
    const int a_row = (lane & 7) + ((lane >> 3) & 1) * 8;   // row within 16-row tile
    const int a_koff = (lane >> 4) * 8;                     // 0 or 8
    const int b_nrow = (lane & 7) + ((lane >> 4) << 3);     // n within 16-col group
    const int b_koff = ((lane >> 3) & 1) * 8;               // 0 or 8

    const int ntiles = (K + BK - 1) / BK;
    for (int kt = 0; kt < ntiles; kt++) {
        const int k0 = kt * BK;

        // ---- stage A tile: 4 float4-equivalents per thread, split hi/lo ----
#pragma unroll
        for (int i = 0; i < 4; i++) {
            int idx = tid + i * 256;          // 0..1023
            int m   = idx >> 3;               // 0..127
            int kq  = (idx & 7) * 4;          // 0..28
            int row = row0 + m;
            float vv[4];
            if (MODE == 0) {
#pragma unroll
                for (int j = 0; j < 4; j++) {
                    int kj = k0 + kq + j;
                    vv[j] = (kj < K) ? ((kj < F_IN) ? X[(size_t)row * F_IN + kj]
                                                    : Gemb[sgid[m] * EMB + (kj - F_IN)])
                                     : 0.0f;
                }
            } else if (MODE == 1) {
                float4 a  = *reinterpret_cast<const float4*>(&g_h  [(size_t)row * H_DIM + k0 + kq]);
                float4 b  = *reinterpret_cast<const float4*>(&g_agg[(size_t)row * H_DIM + k0 + kq]);
                float4 sc = *reinterpret_cast<const float4*>(&g_scale[k0 + kq]);
                float4 sh = *reinterpret_cast<const float4*>(&g_shift[k0 + kq]);
                vv[0] = fmaf(a.x, sc.x, sh.x) + b.x;
                vv[1] = fmaf(a.y, sc.y, sh.y) + b.y;
                vv[2] = fmaf(a.z, sc.z, sh.z) + b.z;
                vv[3] = fmaf(a.w, sc.w, sh.w) + b.w;
            } else {
                float4 a = *reinterpret_cast<const float4*>(&g_tmp[(size_t)row * H_DIM + k0 + kq]);
                vv[0] = a.x; vv[1] = a.y; vv[2] = a.z; vv[3] = a.w;
            }
            __nv_bfloat16 h0,h1,h2,h3,l0,l1,l2,l3;
            split_bf16(vv[0], h0, l0); split_bf16(vv[1], h1, l1);
            split_bf16(vv[2], h2, l2); split_bf16(vv[3], h3, l3);
            __nv_bfloat162* ph = reinterpret_cast<__nv_bfloat162*>(&As_hi[m * ASTR + kq]);
            __nv_bfloat162* pl = reinterpret_cast<__nv_bfloat162*>(&As_lo[m * ASTR + kq]);
            ph[0] = __nv_bfloat162(h0, h1); ph[1] = __nv_bfloat162(h2, h3);
            pl[0] = __nv_bfloat162(l0, l1); pl[1] = __nv_bfloat162(l2, l3);
        }
        // ---- stage B tile transposed to [n][k]: 4 float4 per thread ----
#pragma unroll
        for (int i = 0; i < 4; i++) {
            int idx = tid + i * 256;          // 0..1023
            int kk  = idx >> 5;               // 0..31
            int n   = (idx & 31) * 4;         // 0..124
            int k   = k0 + kk;
            float4 v = make_float4(0.f, 0.f, 0.f, 0.f);
            if (k < K)
                v = *reinterpret_cast<const float4*>(&W[(size_t)k * H_DIM + col0 + n]);
            float vj[4] = { v.x, v.y, v.z, v.w };
#pragma unroll
            for (int j = 0; j < 4; j++) {
                __nv_bfloat16 hi, lo;
                split_bf16(vj[j], hi, lo);
                Bs_hi[(n + j) * ASTR + kk] = hi;
                Bs_lo[(n + j) * ASTR + kk] = lo;
            }
        }
        __syncthreads();

        // ---- mainloop: 2 k16 steps ----
#pragma unroll
        for (int ks = 0; ks < 2; ks++) {
            const int kb = ks * 16;
            unsigned ah[2][4], al[2][4];
#pragma unroll
            for (int mt = 0; mt < 2; mt++) {
                unsigned off = ((wm + mt * 16 + a_row) * ASTR + kb + a_koff) * 2;
                ldsm_x4(ah[mt][0], ah[mt][1], ah[mt][2], ah[mt][3], as_hi_b + off);
                ldsm_x4(al[mt][0], al[mt][1], al[mt][2], al[mt][3], as_lo_b + off);
            }
#pragma unroll
            for (int nt2 = 0; nt2 < 4; nt2++) {
                unsigned off = ((wn + nt2 * 16 + b_nrow) * ASTR + kb + b_koff) * 2;
                unsigned bh[4], bl[4];
                ldsm_x4(bh[0], bh[1], bh[2], bh[3], bs_hi_b + off);
                ldsm_x4(bl[0], bl[1], bl[2], bl[3], bs_lo_b + off);
#pragma unroll
                for (int half = 0; half < 2; half++) {
                    int nt = nt2 * 2 + half;
#pragma unroll
                    for (int mt = 0; mt < 2; mt++) {
                        mma_bf16(acc[mt][nt], ah[mt], bh[half*2], bh[half*2+1]); // Ah*Bh
                        mma_bf16(acc[mt][nt], ah[mt], bl[half*2], bl[half*2+1]); // Ah*Bl
                        mma_bf16(acc[mt][nt], al[mt], bh[half*2], bh[half*2+1]); // Al*Bh
                    }
                }
            }
        }
        __syncthreads();
    }

    // ---- epilogue: bias + relu, float2 stores ----
    float* dst = (MODE == 0) ? g_h : (MODE == 1) ? g_tmp : out_param;
    const int cb = (lane & 3) * 2;     // col pair base within n8 tile
#pragma unroll
    for (int nt = 0; nt < 8; nt++) {
        int col = col0 + wn + nt * 8 + cb;
        float bx = bias[col], by = bias[col + 1];
#pragma unroll
        for (int mt = 0; mt < 2; mt++) {
            int r = row0 + wm + mt * 16 + lrow;
            float2 w0 = make_float2(fmaxf(acc[mt][nt][0] + bx, 0.f),
                                    fmaxf(acc[mt][nt][1] + by, 0.f));
            float2 w1 = make_float2(fmaxf(acc[mt][nt][2] + bx, 0.f),
                                    fmaxf(acc[mt][nt][3] + by, 0.f));
            *reinterpret_cast<float2*>(&dst[(size_t)r * H_DIM + col])       = w0;
            *reinterpret_cast<float2*>(&dst[(size_t)(r + 8) * H_DIM + col]) = w1;
        }
    }
}

// ---------------- BatchNorm stats ----------------
__global__ __launch_bounds__(256)
void bn_stats_kernel() {
    int c = threadIdx.x;   // 256 channels
    float s = 0.0f, s2 = 0.0f;
    for (int r = blockIdx.x; r < N_NODES; r += gridDim.x) {
        float v = g_h[(size_t)r * H_DIM + c];
        s += v;
        s2 += v * v;
    }
    atomicAdd(&g_sum[c], s);
    atomicAdd(&g_sumsq[c], s2);
}

__global__ void bn_finalize_kernel(const float* __restrict__ gamma,
                                   const float* __restrict__ beta) {
    int c = threadIdx.x;
    float invN = 1.0f / (float)N_NODES;
    float mu   = g_sum[c] * invN;
    float var  = fmaxf(g_sumsq[c] * invN - mu * mu, 0.0f);
    float rs   = rsqrtf(var + BN_EPS);
    float sc   = rs * gamma[c];
    g_scale[c] = sc;
    g_shift[c] = beta[c] - mu * sc;
}

// ---------------- GINE edge kernel (BN affine fused into gather) ----------------
// warp per edge (grid-stride). lane owns cols [8*lane, 8*lane+8).
__global__ __launch_bounds__(256)
void edge_kernel(const float* __restrict__ ea,
                 const float* __restrict__ We,
                 const float* __restrict__ be)
{
    const int lane   = threadIdx.x & 31;
    const int warp   = (blockIdx.x * blockDim.x + threadIdx.x) >> 5;
    const int nwarps = (gridDim.x * blockDim.x) >> 5;
    const int cbase  = lane * 8;

    float we[E_DIM][8], bvec[8], sc[8], sh[8];
#pragma unroll
    for (int d = 0; d < E_DIM; d++)
#pragma unroll
        for (int j = 0; j < 8; j++)
            we[d][j] = We[d * H_DIM + cbase + j];
#pragma unroll
    for (int j = 0; j < 8; j++) {
        bvec[j] = be[cbase + j];
        sc[j]   = g_scale[cbase + j];
        sh[j]   = g_shift[cbase + j];
    }

    for (int e = warp; e < N_EDGES; e += nwarps) {
        int src = g_src[e];
        int dst = g_dst[e];
        float eav = (lane < E_DIM) ? ea[(size_t)e * E_DIM + lane] : 0.0f;

        float acc[8];
#pragma unroll
        for (int j = 0; j < 8; j++) acc[j] = bvec[j];
#pragma unroll
        for (int d = 0; d < E_DIM; d++) {
            float v = __shfl_sync(0xffffffffu, eav, d);
#pragma unroll
            for (int j = 0; j < 8; j++) acc[j] = fmaf(v, we[d][j], acc[j]);
        }

        const float4* hp = reinterpret_cast<const float4*>(&g_h[(size_t)src * H_DIM + cbase]);
        float4 h0 = hp[0];
        float4 h1 = hp[1];

        float m0 = fmaxf(fmaf(h0.x, sc[0], sh[0]) + acc[0], 0.0f);
        float m1 = fmaxf(fmaf(h0.y, sc[1], sh[1]) + acc[1], 0.0f);
        float m2 = fmaxf(fmaf(h0.z, sc[2], sh[2]) + acc[2], 0.0f);
        float m3 = fmaxf(fmaf(h0.w, sc[3], sh[3]) + acc[3], 0.0f);
        float m4 = fmaxf(fmaf(h1.x, sc[4], sh[4]) + acc[4], 0.0f);
        float m5 = fmaxf(fmaf(h1.y, sc[5], sh[5]) + acc[5], 0.0f);
        float m6 = fmaxf(fmaf(h1.z, sc[6], sh[6]) + acc[6], 0.0f);
        float m7 = fmaxf(fmaf(h1.w, sc[7], sh[7]) + acc[7], 0.0f);

        float* ap = &g_agg[(size_t)dst * H_DIM + cbase];
        unsigned long long gaddr = (unsigned long long)__cvta_generic_to_global((void*)ap);
        asm volatile("red.global.add.v4.f32 [%0], {%1,%2,%3,%4};"
                     :: "l"(gaddr), "f"(m0), "f"(m1), "f"(m2), "f"(m3) : "memory");
        asm volatile("red.global.add.v4.f32 [%0], {%1,%2,%3,%4};"
                     :: "l"(gaddr + 16), "f"(m4), "f"(m5), "f"(m6), "f"(m7) : "memory");
    }
}

// ---------------- edge_attr passthrough (2nd tuple element) ----------------
__global__ __launch_bounds__(256)
void copy_kernel(const float* __restrict__ src, float* __restrict__ dst, size_t n4) {
    size_t stride = (size_t)gridDim.x * blockDim.x;
    const float4* s4 = reinterpret_cast<const float4*>(src);
    float4* d4 = reinterpret_cast<float4*>(dst);
    for (size_t i = (size_t)blockIdx.x * blockDim.x + threadIdx.x; i < n4; i += stride)
        d4[i] = s4[i];
}

// ---------------- launch ----------------
extern "C" void kernel_launch(void* const* d_in, const int* in_sizes, int n_in,
                              void* d_out, int out_size)
{
    // ---- input order detection by size signature ----
    static const long long SZ_DICT[15] = {
        6889472LL, 1900544LL, 4751360LL, 59392LL, 128LL, 33792LL, 256LL,
        256LL, 256LL, 1280LL, 256LL, 65536LL, 256LL, 65536LL, 256LL };
    static const long long SZ_ALPHA[15] = {
        65536LL, 65536LL, 33792LL, 1280LL, 256LL, 256LL, 256LL, 256LL,
        256LL, 4751360LL, 1900544LL, 256LL, 128LL, 59392LL, 6889472LL };
    static const int ALPHA_TO_DICT[15] = { 11, 13, 5, 9, 12, 14, 6, 10, 8, 2, 1, 7, 4, 3, 0 };

    int perm[15];
    for (int i = 0; i < 15; i++) perm[i] = i;
    if (n_in >= 15) {
        bool dict_ok = true, alpha_ok = true;
        for (int i = 0; i < 15; i++) {
            if ((long long)in_sizes[i] != SZ_DICT[i])  dict_ok  = false;
            if ((long long)in_sizes[i] != SZ_ALPHA[i]) alpha_ok = false;
        }
        if (!dict_ok && alpha_ok)
            for (int i = 0; i < 15; i++) perm[ALPHA_TO_DICT[i]] = i;
    }

    const float* x      = (const float*)d_in[perm[0]];
    const void*  eindex = d_in[perm[1]];
    const float* eattr  = (const float*)d_in[perm[2]];
    const void*  gids   = d_in[perm[3]];
    const float* gemb   = (const float*)d_in[perm[4]];
    const float* W_in   = (const float*)d_in[perm[5]];
    const float* b_in   = (const float*)d_in[perm[6]];
    const float* gamma  = (const float*)d_in[perm[7]];
    const float* beta   = (const float*)d_in[perm[8]];
    const float* We     = (const float*)d_in[perm[9]];
    const float* be     = (const float*)d_in[perm[10]];
    const float* W1     = (const float*)d_in[perm[11]];
    const float* b1     = (const float*)d_in[perm[12]];
    const float* W2     = (const float*)d_in[perm[13]];
    const float* b2     = (const float*)d_in[perm[14]];
    float* out = (float*)d_out;

    dim3 ggrid(N_NODES / 128, H_DIM / 128);   // (464, 2)

    // 0. dtype probe + index normalization (int64 vs int32)
    detect_kernel<<<1, 32>>>((const int*)eindex);
    convert_kernel<<<2048, 256>>>(eindex, gids);

    // 1. zero agg + stats
    zero_kernel<<<2048, 256>>>();

    // 2. h = relu(concat(x, emb) @ W_in + b_in)   -> g_h (raw, pre-BN)
    gemm_kernel<0><<<ggrid, 256>>>(x, gemb, W_in, b_in, nullptr, K_IN);

    // 3-4. BatchNorm stats + affine coefficients (apply is fused downstream)
    bn_stats_kernel<<<464, 256>>>();
    bn_finalize_kernel<<<1, 256>>>(gamma, beta);

    // 5. GINE edge scatter: agg[dst] += relu(bn(h[src]) + ea@We + be)
    edge_kernel<<<4096, 256>>>(eattr, We, be);

    // 6. tmp = relu((bn(h) + agg) @ W1 + b1)   -> g_tmp
    gemm_kernel<1><<<ggrid, 256>>>(nullptr, nullptr, W1, b1, nullptr, H_DIM);

    // 7. out = relu(tmp @ W2 + b2)             -> d_out
    gemm_kernel<2><<<ggrid, 256>>>(nullptr, nullptr, W2, b2, out, H_DIM);

    // 8. second tuple element: edge_attr passthrough
    long long tail = (long long)out_size - (long long)N_NODES * H_DIM;
    if (tail > 0) {
        size_t n4 = (size_t)tail / 4;
        copy_kernel<<<2048, 256>>>(eattr, out + (size_t)N_NODES * H_DIM, n4);
    }
}

// round 7
// speedup vs baseline: 1.0953x; 1.0953x over previous
#include <cuda_runtime.h>
#include <cstdint>

#define N_NODES 59392
#define F_IN    116
#define H_DIM   256
#define N_EDGES 950272
#define E_DIM   5
#define EMB     16
#define K_IN    (F_IN + EMB)   // 132
#define BN_EPS  1e-5f

// ---------------- scratch (no allocations allowed) ----------------
__device__ float g_h  [(size_t)N_NODES * H_DIM];
__device__ float g_agg[(size_t)N_NODES * H_DIM];
__device__ float g_tmp[(size_t)N_NODES * H_DIM];
__device__ float g_sum[H_DIM];
__device__ float g_sumsq[H_DIM];
__device__ float g_scale[H_DIM];
__device__ float g_shift[H_DIM];
__device__ int   g_src[N_EDGES];
__device__ int   g_dst[N_EDGES];
__device__ int   g_gid[N_NODES];
__device__ int   g_is64;

// ---------------- dtype probe: int64 vs int32 index buffers ----------------
__global__ void detect_kernel(const int* __restrict__ ei_words) {
    if (threadIdx.x == 0) {
        int all_zero = 1;
        for (int i = 1; i < 256; i += 2)
            if (ei_words[i] != 0) { all_zero = 0; break; }
        g_is64 = all_zero;
    }
}

// normalize edge_index and group_ids into int32 scratch (works for both dtypes)
__global__ __launch_bounds__(256)
void convert_kernel(const void* __restrict__ ei, const void* __restrict__ gid) {
    const int is64 = g_is64;
    const long long* ei64  = (const long long*)ei;
    const int*       ei32  = (const int*)ei;
    const long long* gid64 = (const long long*)gid;
    const int*       gid32 = (const int*)gid;
    size_t stride = (size_t)gridDim.x * blockDim.x;
    for (size_t e = (size_t)blockIdx.x * blockDim.x + threadIdx.x; e < N_EDGES; e += stride) {
        if (is64) {
            g_src[e] = (int)ei64[e];
            g_dst[e] = (int)ei64[(size_t)N_EDGES + e];
        } else {
            g_src[e] = ei32[e];
            g_dst[e] = ei32[(size_t)N_EDGES + e];
        }
    }
    for (size_t n = (size_t)blockIdx.x * blockDim.x + threadIdx.x; n < N_NODES; n += stride)
        g_gid[n] = is64 ? (int)gid64[n] : gid32[n];
}

// ---------------- zero agg + stats ----------------
__global__ __launch_bounds__(256)
void zero_kernel() {
    size_t total4 = (size_t)N_NODES * H_DIM / 4;
    size_t stride = (size_t)gridDim.x * blockDim.x;
    float4* a4 = reinterpret_cast<float4*>(g_agg);
    float4 z = make_float4(0.f, 0.f, 0.f, 0.f);
    for (size_t i = (size_t)blockIdx.x * blockDim.x + threadIdx.x; i < total4; i += stride)
        a4[i] = z;
    if (blockIdx.x == 0 && threadIdx.x < H_DIM) {
        g_sum[threadIdx.x]   = 0.0f;
        g_sumsq[threadIdx.x] = 0.0f;
    }
}

// ---------------- f32x2 packed-FMA tiled GEMM (R4 config, measured best) ----
// dst[M x 256] = relu(A[M x K] @ W[K x 256] + bias)
// MODE 0: A = concat(x, group_emb[g_gid])      (K = 132), dst = g_h (pre-BN)
// MODE 1: A = bn(g_h) + g_agg                  (K = 256), dst = g_tmp
// MODE 2: A = g_tmp                            (K = 256), dst = out param
// BM=128, BN=128, BK=16, 256 threads, 8x8 micro-tile via 4x8 f32x2 pairs.
template <int MODE>
__global__ __launch_bounds__(256, 2)
void gemm_kernel(const float* __restrict__ X,
                 const float* __restrict__ Gemb,
                 const float* __restrict__ W,
                 const float* __restrict__ bias,
                 float* __restrict__ out_param,
                 int K)
{
    const int BM = 128, BN = 128, BK = 16;
    __shared__ __align__(16) float As[BK][BM + 2];   // k-major, pad 2 (conflict-free)
    __shared__ __align__(16) float Bs[BK][BN];
    __shared__ int sgid[BM];

    const int row0 = blockIdx.x * BM;
    const int col0 = blockIdx.y * BN;
    const int tid  = threadIdx.x;
    const int tx   = tid & 15;    // column group
    const int ty   = tid >> 4;    // row group (8 rows)

    if (MODE == 0) {
        if (tid < BM) sgid[tid] = g_gid[row0 + tid];
        __syncthreads();
    }

    // acc[rp][c]: packed pair = (row 2rp, row 2rp+1) within ty's 8 rows.
    // c<4 -> col = col0 + tx*4 + c ; c>=4 -> col = col0 + 64 + tx*4 + (c-4)
    unsigned long long acc[4][8];
#pragma unroll
    for (int rp = 0; rp < 4; rp++)
#pragma unroll
        for (int c = 0; c < 8; c++) acc[rp][c] = 0ULL;

    const int ntiles = (K + BK - 1) / BK;
    for (int kt = 0; kt < ntiles; kt++) {
        const int k0 = kt * BK;

        // ---- stage A tile (transposed to As[k][m]) : 2 x float4 per thread ----
#pragma unroll
        for (int i = 0; i < 2; i++) {
            int idx = tid + i * 256;          // 0..511
            int m   = idx >> 2;               // 0..127
            int kq  = idx & 3;                // float4 index within BK
            int k   = k0 + kq * 4;
            int row = row0 + m;
            float4 v;
            if (MODE == 0) {
                float vv[4];
#pragma unroll
                for (int j = 0; j < 4; j++) {
                    int kj = k + j;
                    vv[j] = (kj < K) ? ((kj < F_IN) ? X[(size_t)row * F_IN + kj]
                                                    : Gemb[sgid[m] * EMB + (kj - F_IN)])
                                     : 0.0f;
                }
                v = make_float4(vv[0], vv[1], vv[2], vv[3]);
            } else if (MODE == 1) {
                float4 a  = *reinterpret_cast<const float4*>(&g_h  [(size_t)row * H_DIM + k]);
                float4 b  = *reinterpret_cast<const float4*>(&g_agg[(size_t)row * H_DIM + k]);
                float4 sc = *reinterpret_cast<const float4*>(&g_scale[k]);
                float4 sh = *reinterpret_cast<const float4*>(&g_shift[k]);
                v = make_float4(fmaf(a.x, sc.x, sh.x) + b.x,
                                fmaf(a.y, sc.y, sh.y) + b.y,
                                fmaf(a.z, sc.z, sh.z) + b.z,
                                fmaf(a.w, sc.w, sh.w) + b.w);
            } else {
                v = *reinterpret_cast<const float4*>(&g_tmp[(size_t)row * H_DIM + k]);
            }
            As[kq * 4 + 0][m] = v.x;
            As[kq * 4 + 1][m] = v.y;
            As[kq * 4 + 2][m] = v.z;
            As[kq * 4 + 3][m] = v.w;
        }
        // ---- stage B tile : 2 x float4 per thread ----
#pragma unroll
        for (int i = 0; i < 2; i++) {
            int idx = tid + i * 256;          // 0..511
            int kk  = idx >> 5;               // 0..15
            int n   = (idx & 31) * 4;         // 0..124
            int k   = k0 + kk;
            float4 v = make_float4(0.f, 0.f, 0.f, 0.f);
            if (k < K)
                v = *reinterpret_cast<const float4*>(&W[(size_t)k * H_DIM + col0 + n]);
            *reinterpret_cast<float4*>(&Bs[kk][n]) = v;
        }
        __syncthreads();

        // ---- inner product over BK ----
#pragma unroll
        for (int kk = 0; kk < BK; kk++) {
            // a pairs: direct 8-byte loads (rows are contiguous in As)
            const unsigned long long* arow =
                reinterpret_cast<const unsigned long long*>(&As[kk][ty * 8]);
            unsigned long long a2[4];
#pragma unroll
            for (int rp = 0; rp < 4; rp++) a2[rp] = arow[rp];

            float4 b0 = *reinterpret_cast<const float4*>(&Bs[kk][tx * 4]);
            float4 b1 = *reinterpret_cast<const float4*>(&Bs[kk][64 + tx * 4]);

            unsigned long long bb[8];
            {
                unsigned r;
                r = __float_as_uint(b0.x); asm("mov.b64 %0, {%1,%1};" : "=l"(bb[0]) : "r"(r));
                r = __float_as_uint(b0.y); asm("mov.b64 %0, {%1,%1};" : "=l"(bb[1]) : "r"(r));
                r = __float_as_uint(b0.z); asm("mov.b64 %0, {%1,%1};" : "=l"(bb[2]) : "r"(r));
                r = __float_as_uint(b0.w); asm("mov.b64 %0, {%1,%1};" : "=l"(bb[3]) : "r"(r));
                r = __float_as_uint(b1.x); asm("mov.b64 %0, {%1,%1};" : "=l"(bb[4]) : "r"(r));
                r = __float_as_uint(b1.y); asm("mov.b64 %0, {%1,%1};" : "=l"(bb[5]) : "r"(r));
                r = __float_as_uint(b1.z); asm("mov.b64 %0, {%1,%1};" : "=l"(bb[6]) : "r"(r));
                r = __float_as_uint(b1.w); asm("mov.b64 %0, {%1,%1};" : "=l"(bb[7]) : "r"(r));
            }
#pragma unroll
            for (int rp = 0; rp < 4; rp++)
#pragma unroll
                for (int c = 0; c < 8; c++)
                    asm("fma.rn.f32x2 %0, %1, %2, %0;"
                        : "+l"(acc[rp][c]) : "l"(a2[rp]), "l"(bb[c]));
        }
        __syncthreads();
    }

    // ---- epilogue: bias + relu ----
    float* dst = (MODE == 0) ? g_h : (MODE == 1) ? g_tmp : out_param;
    float bias0[4], bias1[4];
#pragma unroll
    for (int c = 0; c < 4; c++) {
        bias0[c] = bias[col0 + tx * 4 + c];
        bias1[c] = bias[col0 + 64 + tx * 4 + c];
    }
#pragma unroll
    for (int rp = 0; rp < 4; rp++) {
        int r0 = row0 + ty * 8 + 2 * rp;
        float lo[8], hi[8];
#pragma unroll
        for (int c = 0; c < 8; c++) {
            lo[c] = __uint_as_float((unsigned)(acc[rp][c] & 0xffffffffULL));
            hi[c] = __uint_as_float((unsigned)(acc[rp][c] >> 32));
        }
        float4 w;
        w = make_float4(fmaxf(lo[0] + bias0[0], 0.f), fmaxf(lo[1] + bias0[1], 0.f),
                        fmaxf(lo[2] + bias0[2], 0.f), fmaxf(lo[3] + bias0[3], 0.f));
        *reinterpret_cast<float4*>(&dst[(size_t)r0 * H_DIM + col0 + tx * 4]) = w;
        w = make_float4(fmaxf(lo[4] + bias1[0], 0.f), fmaxf(lo[5] + bias1[1], 0.f),
                        fmaxf(lo[6] + bias1[2], 0.f), fmaxf(lo[7] + bias1[3], 0.f));
        *reinterpret_cast<float4*>(&dst[(size_t)r0 * H_DIM + col0 + 64 + tx * 4]) = w;
        w = make_float4(fmaxf(hi[0] + bias0[0], 0.f), fmaxf(hi[1] + bias0[1], 0.f),
                        fmaxf(hi[2] + bias0[2], 0.f), fmaxf(hi[3] + bias0[3], 0.f));
        *reinterpret_cast<float4*>(&dst[(size_t)(r0 + 1) * H_DIM + col0 + tx * 4]) = w;
        w = make_float4(fmaxf(hi[4] + bias1[0], 0.f), fmaxf(hi[5] + bias1[1], 0.f),
                        fmaxf(hi[6] + bias1[2], 0.f), fmaxf(hi[7] + bias1[3], 0.f));
        *reinterpret_cast<float4*>(&dst[(size_t)(r0 + 1) * H_DIM + col0 + 64 + tx * 4]) = w;
    }
}

// ---------------- BatchNorm stats (apply is fused downstream) ----------------
__global__ __launch_bounds__(256)
void bn_stats_kernel() {
    int c = threadIdx.x;   // 256 channels
    float s = 0.0f, s2 = 0.0f;
    for (int r = blockIdx.x; r < N_NODES; r += gridDim.x) {
        float v = g_h[(size_t)r * H_DIM + c];
        s += v;
        s2 += v * v;
    }
    atomicAdd(&g_sum[c], s);
    atomicAdd(&g_sumsq[c], s2);
}

__global__ void bn_finalize_kernel(const float* __restrict__ gamma,
                                   const float* __restrict__ beta) {
    int c = threadIdx.x;
    float invN = 1.0f / (float)N_NODES;
    float mu   = g_sum[c] * invN;
    float var  = fmaxf(g_sumsq[c] * invN - mu * mu, 0.0f);
    float rs   = rsqrtf(var + BN_EPS);
    float sc   = rs * gamma[c];
    g_scale[c] = sc;
    g_shift[c] = beta[c] - mu * sc;
}

// ---------------- GINE edge kernel (BN affine fused into gather) ----------------
// warp per edge (grid-stride). lane owns cols [8*lane, 8*lane+8).
__global__ __launch_bounds__(256)
void edge_kernel(const float* __restrict__ ea,
                 const float* __restrict__ We,
                 const float* __restrict__ be)
{
    const int lane   = threadIdx.x & 31;
    const int warp   = (blockIdx.x * blockDim.x + threadIdx.x) >> 5;
    const int nwarps = (gridDim.x * blockDim.x) >> 5;
    const int cbase  = lane * 8;

    float we[E_DIM][8], bvec[8], sc[8], sh[8];
#pragma unroll
    for (int d = 0; d < E_DIM; d++)
#pragma unroll
        for (int j = 0; j < 8; j++)
            we[d][j] = We[d * H_DIM + cbase + j];
#pragma unroll
    for (int j = 0; j < 8; j++) {
        bvec[j] = be[cbase + j];
        sc[j]   = g_scale[cbase + j];
        sh[j]   = g_shift[cbase + j];
    }

    for (int e = warp; e < N_EDGES; e += nwarps) {
        int src = g_src[e];
        int dst = g_dst[e];
        float eav = (lane < E_DIM) ? ea[(size_t)e * E_DIM + lane] : 0.0f;

        float acc[8];
#pragma unroll
        for (int j = 0; j < 8; j++) acc[j] = bvec[j];
#pragma unroll
        for (int d = 0; d < E_DIM; d++) {
            float v = __shfl_sync(0xffffffffu, eav, d);
#pragma unroll
            for (int j = 0; j < 8; j++) acc[j] = fmaf(v, we[d][j], acc[j]);
        }

        const float4* hp = reinterpret_cast<const float4*>(&g_h[(size_t)src * H_DIM + cbase]);
        float4 h0 = hp[0];
        float4 h1 = hp[1];

        float m0 = fmaxf(fmaf(h0.x, sc[0], sh[0]) + acc[0], 0.0f);
        float m1 = fmaxf(fmaf(h0.y, sc[1], sh[1]) + acc[1], 0.0f);
        float m2 = fmaxf(fmaf(h0.z, sc[2], sh[2]) + acc[2], 0.0f);
        float m3 = fmaxf(fmaf(h0.w, sc[3], sh[3]) + acc[3], 0.0f);
        float m4 = fmaxf(fmaf(h1.x, sc[4], sh[4]) + acc[4], 0.0f);
        float m5 = fmaxf(fmaf(h1.y, sc[5], sh[5]) + acc[5], 0.0f);
        float m6 = fmaxf(fmaf(h1.z, sc[6], sh[6]) + acc[6], 0.0f);
        float m7 = fmaxf(fmaf(h1.w, sc[7], sh[7]) + acc[7], 0.0f);

        float* ap = &g_agg[(size_t)dst * H_DIM + cbase];
        unsigned long long gaddr = (unsigned long long)__cvta_generic_to_global((void*)ap);
        asm volatile("red.global.add.v4.f32 [%0], {%1,%2,%3,%4};"
                     :: "l"(gaddr), "f"(m0), "f"(m1), "f"(m2), "f"(m3) : "memory");
        asm volatile("red.global.add.v4.f32 [%0], {%1,%2,%3,%4};"
                     :: "l"(gaddr + 16), "f"(m4), "f"(m5), "f"(m6), "f"(m7) : "memory");
    }
}

// ---------------- edge_attr passthrough (2nd tuple element) ----------------
__global__ __launch_bounds__(256)
void copy_kernel(const float* __restrict__ src, float* __restrict__ dst, size_t n4) {
    size_t stride = (size_t)gridDim.x * blockDim.x;
    const float4* s4 = reinterpret_cast<const float4*>(src);
    float4* d4 = reinterpret_cast<float4*>(dst);
    for (size_t i = (size_t)blockIdx.x * blockDim.x + threadIdx.x; i < n4; i += stride)
        d4[i] = s4[i];
}

// ---------------- launch ----------------
extern "C" void kernel_launch(void* const* d_in, const int* in_sizes, int n_in,
                              void* d_out, int out_size)
{
    // ---- input order detection by size signature ----
    static const long long SZ_DICT[15] = {
        6889472LL, 1900544LL, 4751360LL, 59392LL, 128LL, 33792LL, 256LL,
        256LL, 256LL, 1280LL, 256LL, 65536LL, 256LL, 65536LL, 256LL };
    static const long long SZ_ALPHA[15] = {
        65536LL, 65536LL, 33792LL, 1280LL, 256LL, 256LL, 256LL, 256LL,
        256LL, 4751360LL, 1900544LL, 256LL, 128LL, 59392LL, 6889472LL };
    static const int ALPHA_TO_DICT[15] = { 11, 13, 5, 9, 12, 14, 6, 10, 8, 2, 1, 7, 4, 3, 0 };

    int perm[15];
    for (int i = 0; i < 15; i++) perm[i] = i;
    if (n_in >= 15) {
        bool dict_ok = true, alpha_ok = true;
        for (int i = 0; i < 15; i++) {
            if ((long long)in_sizes[i] != SZ_DICT[i])  dict_ok  = false;
            if ((long long)in_sizes[i] != SZ_ALPHA[i]) alpha_ok = false;
        }
        if (!dict_ok && alpha_ok)
            for (int i = 0; i < 15; i++) perm[ALPHA_TO_DICT[i]] = i;
    }

    const float* x      = (const float*)d_in[perm[0]];
    const void*  eindex = d_in[perm[1]];
    const float* eattr  = (const float*)d_in[perm[2]];
    const void*  gids   = d_in[perm[3]];
    const float* gemb   = (const float*)d_in[perm[4]];
    const float* W_in   = (const float*)d_in[perm[5]];
    const float* b_in   = (const float*)d_in[perm[6]];
    const float* gamma  = (const float*)d_in[perm[7]];
    const float* beta   = (const float*)d_in[perm[8]];
    const float* We     = (const float*)d_in[perm[9]];
    const float* be     = (const float*)d_in[perm[10]];
    const float* W1     = (const float*)d_in[perm[11]];
    const float* b1     = (const float*)d_in[perm[12]];
    const float* W2     = (const float*)d_in[perm[13]];
    const float* b2     = (const float*)d_in[perm[14]];
    float* out = (float*)d_out;

    dim3 ggrid(N_NODES / 128, H_DIM / 128);   // (464, 2)

    // 0. dtype probe + index normalization (int64 vs int32)
    detect_kernel<<<1, 32>>>((const int*)eindex);
    convert_kernel<<<2048, 256>>>(eindex, gids);

    // 1. zero agg + stats
    zero_kernel<<<2048, 256>>>();

    // 2. h = relu(concat(x, emb) @ W_in + b_in)   -> g_h (raw, pre-BN)
    gemm_kernel<0><<<ggrid, 256>>>(x, gemb, W_in, b_in, nullptr, K_IN);

    // 3-4. BatchNorm stats + affine coefficients (apply fused into consumers)
    bn_stats_kernel<<<464, 256>>>();
    bn_finalize_kernel<<<1, 256>>>(gamma, beta);

    // 5. GINE edge scatter: agg[dst] += relu(bn(h[src]) + ea@We + be)
    edge_kernel<<<4096, 256>>>(eattr, We, be);

    // 6. tmp = relu((bn(h) + agg) @ W1 + b1)   -> g_tmp
    gemm_kernel<1><<<ggrid, 256>>>(nullptr, nullptr, W1, b1, nullptr, H_DIM);

    // 7. out = relu(tmp @ W2 + b2)             -> d_out
    gemm_kernel<2><<<ggrid, 256>>>(nullptr, nullptr, W2, b2, out, H_DIM);

    // 8. second tuple element: edge_attr passthrough
    long long tail = (long long)out_size - (long long)N_NODES * H_DIM;
    if (tail > 0) {
        size_t n4 = (size_t)tail / 4;
        copy_kernel<<<2048, 256>>>(eattr, out + (size_t)N_NODES * H_DIM, n4);
    }
}

// round 8
// speedup vs baseline: 1.1244x; 1.0266x over previous
#include <cuda_runtime.h>
#include <cstdint>

#define N_NODES 59392
#define F_IN    116
#define H_DIM   256
#define N_EDGES 950272
#define E_DIM   5
#define EMB     16
#define K_IN    (F_IN + EMB)   // 132
#define BN_EPS  1e-5f

// ---------------- scratch (no allocations allowed) ----------------
__device__ float g_h  [(size_t)N_NODES * H_DIM];
__device__ float g_agg[(size_t)N_NODES * H_DIM];
__device__ float g_tmp[(size_t)N_NODES * H_DIM];
__device__ float g_sum[H_DIM];
__device__ float g_sumsq[H_DIM];
__device__ float g_scale[H_DIM];
__device__ float g_shift[H_DIM];
__device__ int   g_src[N_EDGES];
__device__ int   g_dst[N_EDGES];
__device__ int   g_gid[N_NODES];
__device__ int   g_is64;

// ---------------- cp.async helpers ----------------
__device__ __forceinline__ unsigned sptr(const void* p) {
    return (unsigned)__cvta_generic_to_shared(p);
}
__device__ __forceinline__ void cp_async16(unsigned saddr, const float* g) {
    asm volatile("cp.async.cg.shared.global [%0], [%1], 16;" :: "r"(saddr), "l"(g));
}

// ---------------- dtype probe: int64 vs int32 index buffers ----------------
__global__ void detect_kernel(const int* __restrict__ ei_words) {
    if (threadIdx.x == 0) {
        int all_zero = 1;
        for (int i = 1; i < 256; i += 2)
            if (ei_words[i] != 0) { all_zero = 0; break; }
        g_is64 = all_zero;
    }
}

// normalize indices into int32 scratch + zero agg/stat accumulators (fused)
__global__ __launch_bounds__(256)
void convert_kernel(const void* __restrict__ ei, const void* __restrict__ gid) {
    const int is64 = g_is64;
    const long long* ei64  = (const long long*)ei;
    const int*       ei32  = (const int*)ei;
    const long long* gid64 = (const long long*)gid;
    const int*       gid32 = (const int*)gid;
    size_t stride = (size_t)gridDim.x * blockDim.x;
    size_t t0 = (size_t)blockIdx.x * blockDim.x + threadIdx.x;
    for (size_t e = t0; e < N_EDGES; e += stride) {
        if (is64) {
            g_src[e] = (int)ei64[e];
            g_dst[e] = (int)ei64[(size_t)N_EDGES + e];
        } else {
            g_src[e] = ei32[e];
            g_dst[e] = ei32[(size_t)N_EDGES + e];
        }
    }
    for (size_t n = t0; n < N_NODES; n += stride)
        g_gid[n] = is64 ? (int)gid64[n] : gid32[n];
    // zero agg (float4) + stats
    size_t total4 = (size_t)N_NODES * H_DIM / 4;
    float4* a4 = reinterpret_cast<float4*>(g_agg);
    float4 z = make_float4(0.f, 0.f, 0.f, 0.f);
    for (size_t i = t0; i < total4; i += stride) a4[i] = z;
    if (blockIdx.x == 0 && threadIdx.x < H_DIM) {
        g_sum[threadIdx.x]   = 0.0f;
        g_sumsq[threadIdx.x] = 0.0f;
    }
}

// ---------------- GEMM 0: f32x2 packed FMA, single-buffer (R4, measured) ----
// g_h = relu(concat(x, group_emb[g_gid]) @ W_in + b_in),  K = 132
__global__ __launch_bounds__(256, 2)
void gemm0_kernel(const float* __restrict__ X,
                  const float* __restrict__ Gemb,
                  const float* __restrict__ W,
                  const float* __restrict__ bias)
{
    const int BM = 128, BN = 128, BK = 16, K = K_IN;
    __shared__ __align__(16) float As[BK][BM + 2];
    __shared__ __align__(16) float Bs[BK][BN];
    __shared__ int sgid[BM];

    const int row0 = blockIdx.x * BM;
    const int col0 = blockIdx.y * BN;
    const int tid  = threadIdx.x;
    const int tx   = tid & 15;
    const int ty   = tid >> 4;

    if (tid < BM) sgid[tid] = g_gid[row0 + tid];
    __syncthreads();

    unsigned long long acc[4][8];
#pragma unroll
    for (int rp = 0; rp < 4; rp++)
#pragma unroll
        for (int c = 0; c < 8; c++) acc[rp][c] = 0ULL;

    const int ntiles = (K + BK - 1) / BK;
    for (int kt = 0; kt < ntiles; kt++) {
        const int k0 = kt * BK;
#pragma unroll
        for (int i = 0; i < 2; i++) {
            int idx = tid + i * 256;
            int m   = idx >> 2;
            int kq  = idx & 3;
            int k   = k0 + kq * 4;
            int row = row0 + m;
            float vv[4];
#pragma unroll
            for (int j = 0; j < 4; j++) {
                int kj = k + j;
                vv[j] = (kj < K) ? ((kj < F_IN) ? X[(size_t)row * F_IN + kj]
                                                : Gemb[sgid[m] * EMB + (kj - F_IN)])
                                 : 0.0f;
            }
            As[kq * 4 + 0][m] = vv[0];
            As[kq * 4 + 1][m] = vv[1];
            As[kq * 4 + 2][m] = vv[2];
            As[kq * 4 + 3][m] = vv[3];
        }
#pragma unroll
        for (int i = 0; i < 2; i++) {
            int idx = tid + i * 256;
            int kk  = idx >> 5;
            int n   = (idx & 31) * 4;
            int k   = k0 + kk;
            float4 v = make_float4(0.f, 0.f, 0.f, 0.f);
            if (k < K)
                v = *reinterpret_cast<const float4*>(&W[(size_t)k * H_DIM + col0 + n]);
            *reinterpret_cast<float4*>(&Bs[kk][n]) = v;
        }
        __syncthreads();

#pragma unroll
        for (int kk = 0; kk < BK; kk++) {
            const unsigned long long* arow =
                reinterpret_cast<const unsigned long long*>(&As[kk][ty * 8]);
            unsigned long long a2[4];
#pragma unroll
            for (int rp = 0; rp < 4; rp++) a2[rp] = arow[rp];

            float4 b0 = *reinterpret_cast<const float4*>(&Bs[kk][tx * 4]);
            float4 b1 = *reinterpret_cast<const float4*>(&Bs[kk][64 + tx * 4]);
            unsigned long long bb[8];
            {
                unsigned r;
                r = __float_as_uint(b0.x); asm("mov.b64 %0, {%1,%1};" : "=l"(bb[0]) : "r"(r));
                r = __float_as_uint(b0.y); asm("mov.b64 %0, {%1,%1};" : "=l"(bb[1]) : "r"(r));
                r = __float_as_uint(b0.z); asm("mov.b64 %0, {%1,%1};" : "=l"(bb[2]) : "r"(r));
                r = __float_as_uint(b0.w); asm("mov.b64 %0, {%1,%1};" : "=l"(bb[3]) : "r"(r));
                r = __float_as_uint(b1.x); asm("mov.b64 %0, {%1,%1};" : "=l"(bb[4]) : "r"(r));
                r = __float_as_uint(b1.y); asm("mov.b64 %0, {%1,%1};" : "=l"(bb[5]) : "r"(r));
                r = __float_as_uint(b1.z); asm("mov.b64 %0, {%1,%1};" : "=l"(bb[6]) : "r"(r));
                r = __float_as_uint(b1.w); asm("mov.b64 %0, {%1,%1};" : "=l"(bb[7]) : "r"(r));
            }
#pragma unroll
            for (int rp = 0; rp < 4; rp++)
#pragma unroll
                for (int c = 0; c < 8; c++)
                    asm("fma.rn.f32x2 %0, %1, %2, %0;"
                        : "+l"(acc[rp][c]) : "l"(a2[rp]), "l"(bb[c]));
        }
        __syncthreads();
    }

    float bias0[4], bias1[4];
#pragma unroll
    for (int c = 0; c < 4; c++) {
        bias0[c] = bias[col0 + tx * 4 + c];
        bias1[c] = bias[col0 + 64 + tx * 4 + c];
    }
#pragma unroll
    for (int rp = 0; rp < 4; rp++) {
        int r0 = row0 + ty * 8 + 2 * rp;
        float lo[8], hi[8];
#pragma unroll
        for (int c = 0; c < 8; c++) {
            lo[c] = __uint_as_float((unsigned)(acc[rp][c] & 0xffffffffULL));
            hi[c] = __uint_as_float((unsigned)(acc[rp][c] >> 32));
        }
        float4 w;
        w = make_float4(fmaxf(lo[0] + bias0[0], 0.f), fmaxf(lo[1] + bias0[1], 0.f),
                        fmaxf(lo[2] + bias0[2], 0.f), fmaxf(lo[3] + bias0[3], 0.f));
        *reinterpret_cast<float4*>(&g_h[(size_t)r0 * H_DIM + col0 + tx * 4]) = w;
        w = make_float4(fmaxf(lo[4] + bias1[0], 0.f), fmaxf(lo[5] + bias1[1], 0.f),
                        fmaxf(lo[6] + bias1[2], 0.f), fmaxf(lo[7] + bias1[3], 0.f));
        *reinterpret_cast<float4*>(&g_h[(size_t)r0 * H_DIM + col0 + 64 + tx * 4]) = w;
        w = make_float4(fmaxf(hi[0] + bias0[0], 0.f), fmaxf(hi[1] + bias0[1], 0.f),
                        fmaxf(hi[2] + bias0[2], 0.f), fmaxf(hi[3] + bias0[3], 0.f));
        *reinterpret_cast<float4*>(&g_h[(size_t)(r0 + 1) * H_DIM + col0 + tx * 4]) = w;
        w = make_float4(fmaxf(hi[4] + bias1[0], 0.f), fmaxf(hi[5] + bias1[1], 0.f),
                        fmaxf(hi[6] + bias1[2], 0.f), fmaxf(hi[7] + bias1[3], 0.f));
        *reinterpret_cast<float4*>(&g_h[(size_t)(r0 + 1) * H_DIM + col0 + 64 + tx * 4]) = w;
    }
}

// ---------------- GEMM 1/2: cp.async double-buffered, K = 256 ----------------
// MODE 1: A = bn(g_h) + g_agg -> dst g_tmp
// MODE 2: A = g_tmp           -> dst out_param
template <int MODE>
__global__ __launch_bounds__(256, 2)
void gemm_async_kernel(const float* __restrict__ W,
                       const float* __restrict__ bias,
                       float* __restrict__ out_param)
{
    const int BK = 16, NT = H_DIM / BK;   // 16 tiles
    __shared__ __align__(16) float As[2][BK][128];
    __shared__ __align__(16) float Bs[2][BK][128];
    __shared__ __align__(16) float Hs[128][BK];
    __shared__ __align__(16) float Gs[128][BK];

    const int row0 = blockIdx.x * 128;
    const int col0 = blockIdx.y * 128;
    const int tid  = threadIdx.x;
    const int tx   = tid & 15;
    const int ty   = tid >> 4;

    const float* Asrc = (MODE == 1) ? g_h : g_tmp;

    unsigned long long acc[4][8];
#pragma unroll
    for (int rp = 0; rp < 4; rp++)
#pragma unroll
        for (int c = 0; c < 8; c++) acc[rp][c] = 0ULL;

    // ---- issue cp.async for tile at k0 into buffer b ----
    auto issue = [&](int k0, int b) {
#pragma unroll
        for (int i = 0; i < 2; i++) {
            int idx = tid + i * 256;
            int m   = idx >> 2;
            int c4  = (idx & 3) * 4;
            cp_async16(sptr(&Hs[m][c4]), &Asrc[(size_t)(row0 + m) * H_DIM + k0 + c4]);
            if (MODE == 1)
                cp_async16(sptr(&Gs[m][c4]), &g_agg[(size_t)(row0 + m) * H_DIM + k0 + c4]);
            int kk = idx >> 5;
            int n  = (idx & 31) * 4;
            cp_async16(sptr(&Bs[b][kk][n]), &W[(size_t)(k0 + kk) * H_DIM + col0 + n]);
        }
        asm volatile("cp.async.commit_group;" ::: "memory");
    };

    // ---- fixup: Hs/Gs -> As[b] (BN affine + agg add + transpose) ----
    auto fixup = [&](int k0, int b) {
#pragma unroll
        for (int i = 0; i < 2; i++) {
            int idx = tid + i * 256;
            int m   = idx >> 2;
            int c4  = (idx & 3) * 4;
            float4 h = *reinterpret_cast<const float4*>(&Hs[m][c4]);
            float4 v;
            if (MODE == 1) {
                float4 g  = *reinterpret_cast<const float4*>(&Gs[m][c4]);
                float4 sc = *reinterpret_cast<const float4*>(&g_scale[k0 + c4]);
                float4 sh = *reinterpret_cast<const float4*>(&g_shift[k0 + c4]);
                v = make_float4(fmaf(h.x, sc.x, sh.x) + g.x,
                                fmaf(h.y, sc.y, sh.y) + g.y,
                                fmaf(h.z, sc.z, sh.z) + g.z,
                                fmaf(h.w, sc.w, sh.w) + g.w);
            } else {
                v = h;
            }
            As[b][c4 + 0][m] = v.x;
            As[b][c4 + 1][m] = v.y;
            As[b][c4 + 2][m] = v.z;
            As[b][c4 + 3][m] = v.w;
        }
    };

    // prologue
    issue(0, 0);
    asm volatile("cp.async.wait_group 0;" ::: "memory");
    fixup(0, 0);
    __syncthreads();

    for (int kt = 0; kt < NT; kt++) {
        const int cur = kt & 1;
        const int nxt = cur ^ 1;
        if (kt < NT - 1) issue((kt + 1) * BK, nxt);

        // ---- compute on As[cur]/Bs[cur] ----
#pragma unroll
        for (int kk = 0; kk < BK; kk++) {
            const unsigned long long* arow =
                reinterpret_cast<const unsigned long long*>(&As[cur][kk][ty * 8]);
            unsigned long long a2[4];
#pragma unroll
            for (int rp = 0; rp < 4; rp++) a2[rp] = arow[rp];

            float4 b0 = *reinterpret_cast<const float4*>(&Bs[cur][kk][tx * 4]);
            float4 b1 = *reinterpret_cast<const float4*>(&Bs[cur][kk][64 + tx * 4]);
            unsigned long long bb[8];
            {
                unsigned r;
                r = __float_as_uint(b0.x); asm("mov.b64 %0, {%1,%1};" : "=l"(bb[0]) : "r"(r));
                r = __float_as_uint(b0.y); asm("mov.b64 %0, {%1,%1};" : "=l"(bb[1]) : "r"(r));
                r = __float_as_uint(b0.z); asm("mov.b64 %0, {%1,%1};" : "=l"(bb[2]) : "r"(r));
                r = __float_as_uint(b0.w); asm("mov.b64 %0, {%1,%1};" : "=l"(bb[3]) : "r"(r));
                r = __float_as_uint(b1.x); asm("mov.b64 %0, {%1,%1};" : "=l"(bb[4]) : "r"(r));
                r = __float_as_uint(b1.y); asm("mov.b64 %0, {%1,%1};" : "=l"(bb[5]) : "r"(r));
                r = __float_as_uint(b1.z); asm("mov.b64 %0, {%1,%1};" : "=l"(bb[6]) : "r"(r));
                r = __float_as_uint(b1.w); asm("mov.b64 %0, {%1,%1};" : "=l"(bb[7]) : "r"(r));
            }
#pragma unroll
            for (int rp = 0; rp < 4; rp++)
#pragma unroll
                for (int c = 0; c < 8; c++)
                    asm("fma.rn.f32x2 %0, %1, %2, %0;"
                        : "+l"(acc[rp][c]) : "l"(a2[rp]), "l"(bb[c]));
        }

        if (kt < NT - 1) {
            asm volatile("cp.async.wait_group 0;" ::: "memory");
            fixup((kt + 1) * BK, nxt);
            __syncthreads();
        }
    }

    // ---- epilogue ----
    float* dst = (MODE == 1) ? g_tmp : out_param;
    float bias0[4], bias1[4];
#pragma unroll
    for (int c = 0; c < 4; c++) {
        bias0[c] = bias[col0 + tx * 4 + c];
        bias1[c] = bias[col0 + 64 + tx * 4 + c];
    }
#pragma unroll
    for (int rp = 0; rp < 4; rp++) {
        int r0 = row0 + ty * 8 + 2 * rp;
        float lo[8], hi[8];
#pragma unroll
        for (int c = 0; c < 8; c++) {
            lo[c] = __uint_as_float((unsigned)(acc[rp][c] & 0xffffffffULL));
            hi[c] = __uint_as_float((unsigned)(acc[rp][c] >> 32));
        }
        float4 w;
        w = make_float4(fmaxf(lo[0] + bias0[0], 0.f), fmaxf(lo[1] + bias0[1], 0.f),
                        fmaxf(lo[2] + bias0[2], 0.f), fmaxf(lo[3] + bias0[3], 0.f));
        *reinterpret_cast<float4*>(&dst[(size_t)r0 * H_DIM + col0 + tx * 4]) = w;
        w = make_float4(fmaxf(lo[4] + bias1[0], 0.f), fmaxf(lo[5] + bias1[1], 0.f),
                        fmaxf(lo[6] + bias1[2], 0.f), fmaxf(lo[7] + bias1[3], 0.f));
        *reinterpret_cast<float4*>(&dst[(size_t)r0 * H_DIM + col0 + 64 + tx * 4]) = w;
        w = make_float4(fmaxf(hi[0] + bias0[0], 0.f), fmaxf(hi[1] + bias0[1], 0.f),
                        fmaxf(hi[2] + bias0[2], 0.f), fmaxf(hi[3] + bias0[3], 0.f));
        *reinterpret_cast<float4*>(&dst[(size_t)(r0 + 1) * H_DIM + col0 + tx * 4]) = w;
        w = make_float4(fmaxf(hi[4] + bias1[0], 0.f), fmaxf(hi[5] + bias1[1], 0.f),
                        fmaxf(hi[6] + bias1[2], 0.f), fmaxf(hi[7] + bias1[3], 0.f));
        *reinterpret_cast<float4*>(&dst[(size_t)(r0 + 1) * H_DIM + col0 + 64 + tx * 4]) = w;
    }
}

// ---------------- BatchNorm stats (apply is fused downstream) ----------------
__global__ __launch_bounds__(256)
void bn_stats_kernel() {
    int c = threadIdx.x;
    float s = 0.0f, s2 = 0.0f;
    for (int r = blockIdx.x; r < N_NODES; r += gridDim.x) {
        float v = g_h[(size_t)r * H_DIM + c];
        s += v;
        s2 += v * v;
    }
    atomicAdd(&g_sum[c], s);
    atomicAdd(&g_sumsq[c], s2);
}

__global__ void bn_finalize_kernel(const float* __restrict__ gamma,
                                   const float* __restrict__ beta) {
    int c = threadIdx.x;
    float invN = 1.0f / (float)N_NODES;
    float mu   = g_sum[c] * invN;
    float var  = fmaxf(g_sumsq[c] * invN - mu * mu, 0.0f);
    float rs   = rsqrtf(var + BN_EPS);
    float sc   = rs * gamma[c];
    g_scale[c] = sc;
    g_shift[c] = beta[c] - mu * sc;
}

// ---------------- GINE edge kernel (BN affine fused into gather) ----------------
__global__ __launch_bounds__(256)
void edge_kernel(const float* __restrict__ ea,
                 const float* __restrict__ We,
                 const float* __restrict__ be)
{
    const int lane   = threadIdx.x & 31;
    const int warp   = (blockIdx.x * blockDim.x + threadIdx.x) >> 5;
    const int nwarps = (gridDim.x * blockDim.x) >> 5;
    const int cbase  = lane * 8;

    float we[E_DIM][8], bvec[8], sc[8], sh[8];
#pragma unroll
    for (int d = 0; d < E_DIM; d++)
#pragma unroll
        for (int j = 0; j < 8; j++)
            we[d][j] = We[d * H_DIM + cbase + j];
#pragma unroll
    for (int j = 0; j < 8; j++) {
        bvec[j] = be[cbase + j];
        sc[j]   = g_scale[cbase + j];
        sh[j]   = g_shift[cbase + j];
    }

    for (int e = warp; e < N_EDGES; e += nwarps) {
        int src = g_src[e];
        int dst = g_dst[e];
        float eav = (lane < E_DIM) ? ea[(size_t)e * E_DIM + lane] : 0.0f;

        float acc[8];
#pragma unroll
        for (int j = 0; j < 8; j++) acc[j] = bvec[j];
#pragma unroll
        for (int d = 0; d < E_DIM; d++) {
            float v = __shfl_sync(0xffffffffu, eav, d);
#pragma unroll
            for (int j = 0; j < 8; j++) acc[j] = fmaf(v, we[d][j], acc[j]);
        }

        const float4* hp = reinterpret_cast<const float4*>(&g_h[(size_t)src * H_DIM + cbase]);
        float4 h0 = hp[0];
        float4 h1 = hp[1];

        float m0 = fmaxf(fmaf(h0.x, sc[0], sh[0]) + acc[0], 0.0f);
        float m1 = fmaxf(fmaf(h0.y, sc[1], sh[1]) + acc[1], 0.0f);
        float m2 = fmaxf(fmaf(h0.z, sc[2], sh[2]) + acc[2], 0.0f);
        float m3 = fmaxf(fmaf(h0.w, sc[3], sh[3]) + acc[3], 0.0f);
        float m4 = fmaxf(fmaf(h1.x, sc[4], sh[4]) + acc[4], 0.0f);
        float m5 = fmaxf(fmaf(h1.y, sc[5], sh[5]) + acc[5], 0.0f);
        float m6 = fmaxf(fmaf(h1.z, sc[6], sh[6]) + acc[6], 0.0f);
        float m7 = fmaxf(fmaf(h1.w, sc[7], sh[7]) + acc[7], 0.0f);

        float* ap = &g_agg[(size_t)dst * H_DIM + cbase];
        unsigned long long gaddr = (unsigned long long)__cvta_generic_to_global((void*)ap);
        asm volatile("red.global.add.v4.f32 [%0], {%1,%2,%3,%4};"
                     :: "l"(gaddr), "f"(m0), "f"(m1), "f"(m2), "f"(m3) : "memory");
        asm volatile("red.global.add.v4.f32 [%0], {%1,%2,%3,%4};"
                     :: "l"(gaddr + 16), "f"(m4), "f"(m5), "f"(m6), "f"(m7) : "memory");
    }
}

// ---------------- edge_attr passthrough (2nd tuple element) ----------------
__global__ __launch_bounds__(256)
void copy_kernel(const float* __restrict__ src, float* __restrict__ dst, size_t n4) {
    size_t stride = (size_t)gridDim.x * blockDim.x;
    const float4* s4 = reinterpret_cast<const float4*>(src);
    float4* d4 = reinterpret_cast<float4*>(dst);
    for (size_t i = (size_t)blockIdx.x * blockDim.x + threadIdx.x; i < n4; i += stride)
        d4[i] = s4[i];
}

// ---------------- launch ----------------
extern "C" void kernel_launch(void* const* d_in, const int* in_sizes, int n_in,
                              void* d_out, int out_size)
{
    // ---- input order detection by size signature ----
    static const long long SZ_DICT[15] = {
        6889472LL, 1900544LL, 4751360LL, 59392LL, 128LL, 33792LL, 256LL,
        256LL, 256LL, 1280LL, 256LL, 65536LL, 256LL, 65536LL, 256LL };
    static const long long SZ_ALPHA[15] = {
        65536LL, 65536LL, 33792LL, 1280LL, 256LL, 256LL, 256LL, 256LL,
        256LL, 4751360LL, 1900544LL, 256LL, 128LL, 59392LL, 6889472LL };
    static const int ALPHA_TO_DICT[15] = { 11, 13, 5, 9, 12, 14, 6, 10, 8, 2, 1, 7, 4, 3, 0 };

    int perm[15];
    for (int i = 0; i < 15; i++) perm[i] = i;
    if (n_in >= 15) {
        bool dict_ok = true, alpha_ok = true;
        for (int i = 0; i < 15; i++) {
            if ((long long)in_sizes[i] != SZ_DICT[i])  dict_ok  = false;
            if ((long long)in_sizes[i] != SZ_ALPHA[i]) alpha_ok = false;
        }
        if (!dict_ok && alpha_ok)
            for (int i = 0; i < 15; i++) perm[ALPHA_TO_DICT[i]] = i;
    }

    const float* x      = (const float*)d_in[perm[0]];
    const void*  eindex = d_in[perm[1]];
    const float* eattr  = (const float*)d_in[perm[2]];
    const void*  gids   = d_in[perm[3]];
    const float* gemb   = (const float*)d_in[perm[4]];
    const float* W_in   = (const float*)d_in[perm[5]];
    const float* b_in   = (const float*)d_in[perm[6]];
    const float* gamma  = (const float*)d_in[perm[7]];
    const float* beta   = (const float*)d_in[perm[8]];
    const float* We     = (const float*)d_in[perm[9]];
    const float* be     = (const float*)d_in[perm[10]];
    const float* W1     = (const float*)d_in[perm[11]];
    const float* b1     = (const float*)d_in[perm[12]];
    const float* W2     = (const float*)d_in[perm[13]];
    const float* b2     = (const float*)d_in[perm[14]];
    float* out = (float*)d_out;

    dim3 ggrid(N_NODES / 128, H_DIM / 128);   // (464, 2)

    // 0. dtype probe + index normalization + zeroing (fused)
    detect_kernel<<<1, 32>>>((const int*)eindex);
    convert_kernel<<<2048, 256>>>(eindex, gids);

    // 1. h = relu(concat(x, emb) @ W_in + b_in)   -> g_h (raw, pre-BN)
    gemm0_kernel<<<ggrid, 256>>>(x, gemb, W_in, b_in);

    // 2-3. BatchNorm stats + affine coefficients (apply fused into consumers)
    bn_stats_kernel<<<464, 256>>>();
    bn_finalize_kernel<<<1, 256>>>(gamma, beta);

    // 4. GINE edge scatter: agg[dst] += relu(bn(h[src]) + ea@We + be)
    edge_kernel<<<4096, 256>>>(eattr, We, be);

    // 5. tmp = relu((bn(h) + agg) @ W1 + b1)   -> g_tmp   (cp.async pipelined)
    gemm_async_kernel<1><<<ggrid, 256>>>(W1, b1, nullptr);

    // 6. out = relu(tmp @ W2 + b2)             -> d_out   (cp.async pipelined)
    gemm_async_kernel<2><<<ggrid, 256>>>(W2, b2, out);

    // 7. second tuple element: edge_attr passthrough
    long long tail = (long long)out_size - (long long)N_NODES * H_DIM;
    if (tail > 0) {
        size_t n4 = (size_t)tail / 4;
        copy_kernel<<<2048, 256>>>(eattr, out + (size_t)N_NODES * H_DIM, n4);
    }
}